// round 3
// baseline (speedup 1.0000x reference)
#include <cuda_runtime.h>
#include <math.h>

#define BSZ   8
#define TLEN  4096
#define EDIM  1024
#define HDIM  128
#define MTOT  (BSZ * TLEN)   // 32768

// Scratch: Q,V row-major [B*T][H]; K transposed [B][H][T].
__device__ float Qg [MTOT * HDIM];
__device__ float Ktg[MTOT * HDIM];
__device__ float Vg [MTOT * HDIM];

// ---------------------------------------------------------------------------
// Kernel 1: projection GEMM.  O[M,128] = X[M,1024] @ W[1024,128]
// BM=128, BN=128, BK=16, 256 threads, 8x8 register tile.
// which: 0 -> Qg (row-major), 1 -> Ktg (transposed [B][H][T]), 2 -> Vg.
// ---------------------------------------------------------------------------
__global__ __launch_bounds__(256) void proj_gemm(const float* __restrict__ X,
                                                 const float* __restrict__ W,
                                                 int which) {
    __shared__ float As[16 * 132];
    __shared__ float Bs[16 * 128];

    const int m0  = blockIdx.x * 128;
    const int tid = threadIdx.x;
    const int tm  = tid >> 4;
    const int tn  = tid & 15;

    float acc[8][8];
#pragma unroll
    for (int i = 0; i < 8; i++)
#pragma unroll
        for (int j = 0; j < 8; j++) acc[i][j] = 0.f;

    for (int k0 = 0; k0 < EDIM; k0 += 16) {
#pragma unroll
        for (int it = 0; it < 2; it++) {
            int idx = tid + it * 256;
            int r   = idx >> 2;
            int c4  = idx & 3;
            float4 v = *(const float4*)(X + (size_t)(m0 + r) * EDIM + k0 + c4 * 4);
            As[(c4 * 4 + 0) * 132 + r] = v.x;
            As[(c4 * 4 + 1) * 132 + r] = v.y;
            As[(c4 * 4 + 2) * 132 + r] = v.z;
            As[(c4 * 4 + 3) * 132 + r] = v.w;
        }
#pragma unroll
        for (int it = 0; it < 2; it++) {
            int idx = tid + it * 256;
            int kk  = idx >> 5;
            int n4  = idx & 31;
            *(float4*)(Bs + kk * 128 + n4 * 4) =
                *(const float4*)(W + (size_t)(k0 + kk) * HDIM + n4 * 4);
        }
        __syncthreads();

#pragma unroll
        for (int kk = 0; kk < 16; kk++) {
            float a[8], b[8];
            *(float4*)(a)     = *(const float4*)(As + kk * 132 + tm * 8);
            *(float4*)(a + 4) = *(const float4*)(As + kk * 132 + tm * 8 + 4);
            *(float4*)(b)     = *(const float4*)(Bs + kk * 128 + tn * 8);
            *(float4*)(b + 4) = *(const float4*)(Bs + kk * 128 + tn * 8 + 4);
#pragma unroll
            for (int i = 0; i < 8; i++)
#pragma unroll
                for (int j = 0; j < 8; j++) acc[i][j] += a[i] * b[j];
        }
        __syncthreads();
    }

    if (which == 1) {
        // K: store transposed into Ktg[b][h][t]
        const int b  = m0 >> 12;                 // 4096 tokens per batch
        const int t0 = (m0 & 4095) + tm * 8;
        float* kb = Ktg + (size_t)b * HDIM * TLEN;
#pragma unroll
        for (int j = 0; j < 8; j++) {
            float* col = kb + (size_t)(tn * 8 + j) * TLEN + t0;
#pragma unroll
            for (int i = 0; i < 8; i++) col[i] = acc[i][j];
        }
    } else {
        float* O = (which == 0) ? Qg : Vg;
#pragma unroll
        for (int i = 0; i < 8; i++) {
            float* orow = O + (size_t)(m0 + tm * 8 + i) * HDIM + tn * 8;
            *(float4*)(orow)     = make_float4(acc[i][0], acc[i][1], acc[i][2], acc[i][3]);
            *(float4*)(orow + 4) = make_float4(acc[i][4], acc[i][5], acc[i][6], acc[i][7]);
        }
    }
}

// ---------------------------------------------------------------------------
// Kernel 2: causal flash attention, BQ=128, BK=128, 256 threads (16x16),
// 8x8 register tiles for both S and O.
// smem: Qs[128][132] + Kt[128][132] (h-major, aliased by P) + Vs[128][132]
//     = 202.75 KB -> 1 block/SM.
// ---------------------------------------------------------------------------
#define QS_ST 132
#define KT_ST 132
#define VS_ST 132
#define PS_ST 132
#define TILE_FLOATS (128 * 132)
#define SMEM_BYTES  (3 * TILE_FLOATS * 4)

__global__ __launch_bounds__(256, 1) void flash_kernel(float* __restrict__ Out) {
    extern __shared__ float sm[];
    float* Qs = sm;
    float* Kt = sm + TILE_FLOATS;
    float* Vs = sm + 2 * TILE_FLOATS;
    float* Ps = Kt;   // alias: Kt dead after S-compute

    const int qt  = 31 - blockIdx.x;   // heavy q-tiles first
    const int b   = blockIdx.y;
    const int tid = threadIdx.x;
    const int ty  = tid >> 4;
    const int tx  = tid & 15;

    const size_t baseQ  = ((size_t)b * TLEN + (size_t)qt * 128) * HDIM;
    const float* ktbase = Ktg + (size_t)b * HDIM * TLEN;

    // Load Q tile (row-major, pre-scaled by 1/sqrt(H))
    const float inv = 0.08838834764831845f;
#pragma unroll
    for (int it = 0; it < 16; it++) {
        int idx = tid + it * 256;          // 0..4095
        int r   = idx >> 5;                // 0..127
        int c4  = idx & 31;
        float4 v = *(const float4*)(Qg + baseQ + (size_t)r * HDIM + c4 * 4);
        v.x *= inv; v.y *= inv; v.z *= inv; v.w *= inv;
        *(float4*)(Qs + r * QS_ST + c4 * 4) = v;
    }

    float o[8][8];
    float mr[8], lr[8];
#pragma unroll
    for (int i = 0; i < 8; i++) {
        mr[i] = -1e30f;
        lr[i] = 0.f;
#pragma unroll
        for (int c = 0; c < 8; c++) o[i][c] = 0.f;
    }

    const float* qb = Qs + (8 * ty) * QS_ST;

    for (int kt = 0; kt <= qt; kt++) {
        // Load K tile (h-major from Ktg: coalesced gmem, dense smem stores)
        const float* ksrc = ktbase + (size_t)kt * 128;
#pragma unroll
        for (int it = 0; it < 16; it++) {
            int idx = tid + it * 256;
            int h   = idx >> 5;            // 0..127
            int c4  = idx & 31;
            float4 v = *(const float4*)(ksrc + (size_t)h * TLEN + c4 * 4);
            *(float4*)(Kt + h * KT_ST + c4 * 4) = v;
        }
        // Load V tile (row-major)
        const size_t baseV = ((size_t)b * TLEN + (size_t)kt * 128) * HDIM;
#pragma unroll
        for (int it = 0; it < 16; it++) {
            int idx = tid + it * 256;
            int r   = idx >> 5;
            int c4  = idx & 31;
            *(float4*)(Vs + r * VS_ST + c4 * 4) =
                *(const float4*)(Vg + baseV + (size_t)r * HDIM + c4 * 4);
        }
        __syncthreads();

        // ---- S = Q K^T : 8x8 per thread, rows 8ty.., cols 8tx.. ----
        float s[8][8];
#pragma unroll
        for (int i = 0; i < 8; i++)
#pragma unroll
            for (int j = 0; j < 8; j++) s[i][j] = 0.f;

#pragma unroll 2
        for (int h4 = 0; h4 < 32; h4++) {
            float qa[8][4];
#pragma unroll
            for (int i = 0; i < 8; i++)
                *(float4*)qa[i] = *(const float4*)(qb + i * QS_ST + 4 * h4);
#pragma unroll
            for (int e = 0; e < 4; e++) {
                float kb[8];
                const float* kr = Kt + (4 * h4 + e) * KT_ST + 8 * tx;
                *(float4*)(kb)     = *(const float4*)(kr);
                *(float4*)(kb + 4) = *(const float4*)(kr + 4);
#pragma unroll
                for (int i = 0; i < 8; i++)
#pragma unroll
                    for (int j = 0; j < 8; j++) s[i][j] += qa[i][e] * kb[j];
            }
        }

        // Causal mask on the diagonal tile
        if (kt == qt) {
#pragma unroll
            for (int i = 0; i < 8; i++)
#pragma unroll
                for (int j = 0; j < 8; j++)
                    if (8 * tx + j > 8 * ty + i) s[i][j] = -1e30f;
        }

        // ---- online softmax (row stats across the 16 tx lanes) ----
#pragma unroll
        for (int i = 0; i < 8; i++) {
            float mt = s[i][0];
#pragma unroll
            for (int j = 1; j < 8; j++) mt = fmaxf(mt, s[i][j]);
            mt = fmaxf(mt, __shfl_xor_sync(0xffffffffu, mt, 8));
            mt = fmaxf(mt, __shfl_xor_sync(0xffffffffu, mt, 4));
            mt = fmaxf(mt, __shfl_xor_sync(0xffffffffu, mt, 2));
            mt = fmaxf(mt, __shfl_xor_sync(0xffffffffu, mt, 1));
            float mnew  = fmaxf(mr[i], mt);
            float alpha = __expf(mr[i] - mnew);
            mr[i] = mnew;
            float rs = 0.f;
#pragma unroll
            for (int j = 0; j < 8; j++) {
                s[i][j] = __expf(s[i][j] - mnew);
                rs += s[i][j];
            }
            rs += __shfl_xor_sync(0xffffffffu, rs, 8);
            rs += __shfl_xor_sync(0xffffffffu, rs, 4);
            rs += __shfl_xor_sync(0xffffffffu, rs, 2);
            rs += __shfl_xor_sync(0xffffffffu, rs, 1);
            lr[i] = lr[i] * alpha + rs;
#pragma unroll
            for (int c = 0; c < 8; c++) o[i][c] *= alpha;
        }

        __syncthreads();   // all Kt reads done before P overwrites it

        // Stage P (aliases Kt)
#pragma unroll
        for (int i = 0; i < 8; i++) {
            float* pr = Ps + (8 * ty + i) * PS_ST + 8 * tx;
            *(float4*)(pr)     = make_float4(s[i][0], s[i][1], s[i][2], s[i][3]);
            *(float4*)(pr + 4) = make_float4(s[i][4], s[i][5], s[i][6], s[i][7]);
        }
        __syncthreads();

        // ---- O += P V : 8x8 per thread, rows 8ty.., h-cols 8tx.. ----
#pragma unroll 2
        for (int j4 = 0; j4 < 32; j4++) {
            float pa[8][4];
#pragma unroll
            for (int i = 0; i < 8; i++)
                *(float4*)pa[i] = *(const float4*)(Ps + (8 * ty + i) * PS_ST + 4 * j4);
#pragma unroll
            for (int e = 0; e < 4; e++) {
                float va[8];
                const float* vr = Vs + (4 * j4 + e) * VS_ST + 8 * tx;
                *(float4*)(va)     = *(const float4*)(vr);
                *(float4*)(va + 4) = *(const float4*)(vr + 4);
#pragma unroll
                for (int i = 0; i < 8; i++)
#pragma unroll
                    for (int c = 0; c < 8; c++) o[i][c] += pa[i][e] * va[c];
            }
        }
        __syncthreads();   // PV done before next tile overwrites Kt/Vs
    }

    // Epilogue
#pragma unroll
    for (int i = 0; i < 8; i++) {
        float rl = 1.f / lr[i];
        float* orow = Out + baseQ + (size_t)(8 * ty + i) * HDIM + 8 * tx;
        *(float4*)(orow)     = make_float4(o[i][0] * rl, o[i][1] * rl, o[i][2] * rl, o[i][3] * rl);
        *(float4*)(orow + 4) = make_float4(o[i][4] * rl, o[i][5] * rl, o[i][6] * rl, o[i][7] * rl);
    }
}

// ---------------------------------------------------------------------------
extern "C" void kernel_launch(void* const* d_in, const int* in_sizes, int n_in,
                              void* d_out, int out_size) {
    const float* x  = (const float*)d_in[0];
    const float* Wq = (const float*)d_in[1];
    const float* Wk = (const float*)d_in[2];
    const float* Wv = (const float*)d_in[3];
    float* out = (float*)d_out;

    (void)in_sizes; (void)n_in; (void)out_size;

    proj_gemm<<<MTOT / 128, 256>>>(x, Wq, 0);
    proj_gemm<<<MTOT / 128, 256>>>(x, Wk, 1);
    proj_gemm<<<MTOT / 128, 256>>>(x, Wv, 2);

    cudaFuncSetAttribute(flash_kernel, cudaFuncAttributeMaxDynamicSharedMemorySize,
                         SMEM_BYTES);
    flash_kernel<<<dim3(32, BSZ), 256, SMEM_BYTES>>>(out);
}

// round 5
// speedup vs baseline: 1.5016x; 1.5016x over previous
#include <cuda_runtime.h>
#include <cuda_bf16.h>
#include <stdint.h>

#define BSZ   8
#define TLEN  4096
#define EDIM  1024
#define HDIM  128
#define MTOT  (BSZ * TLEN)

// bf16 hi/lo operands, all row-major [t][h].
__device__ __nv_bfloat16 Qhi_g[MTOT * HDIM], Qlo_g[MTOT * HDIM];
__device__ __nv_bfloat16 Khi_g[MTOT * HDIM], Klo_g[MTOT * HDIM];
__device__ __nv_bfloat16 Vhi_g[MTOT * HDIM], Vlo_g[MTOT * HDIM];

// ---------------- helpers ----------------
__device__ __forceinline__ uint32_t smem_to_u32(const void* p) {
    uint32_t a;
    asm("{ .reg .u64 t; cvta.to.shared.u64 t, %1; cvt.u32.u64 %0, t; }" : "=r"(a) : "l"(p));
    return a;
}
#define LDSM4(R, A) asm volatile( \
    "ldmatrix.sync.aligned.m8n8.x4.shared.b16 {%0,%1,%2,%3}, [%4];" \
    : "=r"((R)[0]), "=r"((R)[1]), "=r"((R)[2]), "=r"((R)[3]) : "r"(A))
#define LDSM4T(R, A) asm volatile( \
    "ldmatrix.sync.aligned.m8n8.x4.trans.shared.b16 {%0,%1,%2,%3}, [%4];" \
    : "=r"((R)[0]), "=r"((R)[1]), "=r"((R)[2]), "=r"((R)[3]) : "r"(A))
#define MMA(C, A, B) asm volatile( \
    "mma.sync.aligned.m16n8k16.row.col.f32.bf16.bf16.f32 " \
    "{%0,%1,%2,%3},{%4,%5,%6,%7},{%8,%9},{%0,%1,%2,%3};" \
    : "+f"((C)[0]), "+f"((C)[1]), "+f"((C)[2]), "+f"((C)[3]) \
    : "r"((A)[0]), "r"((A)[1]), "r"((A)[2]), "r"((A)[3]), "r"((B)[0]), "r"((B)[1]))
#define CPA(S, G) asm volatile("cp.async.cg.shared.global [%0], [%1], 16;" \
    :: "r"(S), "l"(G))
#define CPC() asm volatile("cp.async.commit_group;")

__device__ __forceinline__ float fexp(float x) {      // FMA-pipe exp, ~2e-6 rel
    float t = x * 1.4426950408889634f;
    float k = rintf(t);
    float u = (t - k) * 0.6931471805599453f;
    float p = 1.f + u * (1.f + u * (0.5f + u * (0.16666667f +
              u * (0.041666667f + u * 0.0083333333f))));
    return p * __int_as_float(((int)k + 127) << 23);
}
__device__ __forceinline__ uint32_t b2u(__nv_bfloat16 a, __nv_bfloat16 b) {
    __nv_bfloat162 t; t.x = a; t.y = b; return *(uint32_t*)&t;
}
__device__ __forceinline__ void splitf(float f, __nv_bfloat16& h, __nv_bfloat16& l) {
    h = __float2bfloat16(f);
    l = __float2bfloat16(f - __bfloat162float(h));
}

// ---------------------------------------------------------------------------
// Kernel 1: projection GEMM (SIMT fp32) + bf16 hi/lo split epilogue.
// grid (256, 3): which=0 Q (scaled), 1 K, 2 V — all row-major.
// ---------------------------------------------------------------------------
__global__ __launch_bounds__(256) void proj_gemm(const float* __restrict__ X,
                                                 const float* __restrict__ Wq,
                                                 const float* __restrict__ Wk,
                                                 const float* __restrict__ Wv) {
    __shared__ float As[16 * 132];
    __shared__ float Bs[16 * 128];
    const int which = blockIdx.y;
    const float* W = (which == 0) ? Wq : (which == 1) ? Wk : Wv;
    const int m0 = blockIdx.x * 128, tid = threadIdx.x;
    const int tm = tid >> 4, tn = tid & 15;

    float acc[8][8];
#pragma unroll
    for (int i = 0; i < 8; i++)
#pragma unroll
        for (int j = 0; j < 8; j++) acc[i][j] = 0.f;

    for (int k0 = 0; k0 < EDIM; k0 += 16) {
#pragma unroll
        for (int it = 0; it < 2; it++) {
            int idx = tid + it * 256, r = idx >> 2, c4 = idx & 3;
            float4 v = *(const float4*)(X + (size_t)(m0 + r) * EDIM + k0 + c4 * 4);
            As[(c4 * 4 + 0) * 132 + r] = v.x;
            As[(c4 * 4 + 1) * 132 + r] = v.y;
            As[(c4 * 4 + 2) * 132 + r] = v.z;
            As[(c4 * 4 + 3) * 132 + r] = v.w;
        }
#pragma unroll
        for (int it = 0; it < 2; it++) {
            int idx = tid + it * 256, kk = idx >> 5, n4 = idx & 31;
            *(float4*)(Bs + kk * 128 + n4 * 4) =
                *(const float4*)(W + (size_t)(k0 + kk) * HDIM + n4 * 4);
        }
        __syncthreads();
#pragma unroll
        for (int kk = 0; kk < 16; kk++) {
            float a[8], bb[8];
            *(float4*)(a)      = *(const float4*)(As + kk * 132 + tm * 8);
            *(float4*)(a + 4)  = *(const float4*)(As + kk * 132 + tm * 8 + 4);
            *(float4*)(bb)     = *(const float4*)(Bs + kk * 128 + tn * 8);
            *(float4*)(bb + 4) = *(const float4*)(Bs + kk * 128 + tn * 8 + 4);
#pragma unroll
            for (int i = 0; i < 8; i++)
#pragma unroll
                for (int j = 0; j < 8; j++) acc[i][j] += a[i] * bb[j];
        }
        __syncthreads();
    }

    const float sc = (which == 0) ? 0.08838834764831845f : 1.0f;
    __nv_bfloat16* dh = (which == 0) ? Qhi_g : (which == 1) ? Khi_g : Vhi_g;
    __nv_bfloat16* dl = (which == 0) ? Qlo_g : (which == 1) ? Klo_g : Vlo_g;
#pragma unroll
    for (int i = 0; i < 8; i++) {
        size_t row = (size_t)(m0 + tm * 8 + i);
        uint32_t hp[4], lp[4];
#pragma unroll
        for (int j2 = 0; j2 < 4; j2++) {
            __nv_bfloat16 h0, l0, h1, l1;
            splitf(acc[i][2 * j2] * sc, h0, l0);
            splitf(acc[i][2 * j2 + 1] * sc, h1, l1);
            hp[j2] = b2u(h0, h1);
            lp[j2] = b2u(l0, l1);
        }
        *(uint4*)(dh + row * HDIM + tn * 8) = make_uint4(hp[0], hp[1], hp[2], hp[3]);
        *(uint4*)(dl + row * HDIM + tn * 8) = make_uint4(lp[0], lp[1], lp[2], lp[3]);
    }
}

// ---------------------------------------------------------------------------
// Kernel 2: FA2-style mma.sync flash. BQ=128 (8 warps x 16 rows), BK=64.
// smem rows padded to 272B (conflict-free ldmatrix). K/V double-buffered.
// ---------------------------------------------------------------------------
#define STR   272
#define QTILE 34816u                 // 128*272
#define SUB   17408u                 // 64*272
#define KVBUF (4 * SUB)              // Khi,Klo,Vhi,Vlo
#define SM_TOT (2 * QTILE + 2 * KVBUF)   // 208896 B

__device__ __forceinline__ void kv_issue(uint32_t dstb, int b, int t0, int tid) {
    const __nv_bfloat16* srcs[4] = {Khi_g, Klo_g, Vhi_g, Vlo_g};
#pragma unroll
    for (int sub = 0; sub < 4; sub++) {
        const __nv_bfloat16* sp = srcs[sub] + ((size_t)b * TLEN + t0) * HDIM;
#pragma unroll
        for (int i = 0; i < 4; i++) {
            int u = tid + i * 256, r = u >> 4, c = u & 15;
            CPA(dstb + sub * SUB + r * STR + c * 16, sp + r * HDIM + c * 8);
        }
    }
}

__global__ __launch_bounds__(256, 1) void flash_mma(float* __restrict__ Out) {
    extern __shared__ char sm[];
    const uint32_t smb = smem_to_u32(sm);
    const int tid = threadIdx.x, w = tid >> 5, l = tid & 31;
    const int qt = 31 - blockIdx.x, b = blockIdx.y;
    const size_t gq0 = (size_t)b * TLEN + (size_t)qt * 128;
    const int nsteps = 2 * qt + 2;

    // Q tile -> smem (hi, lo)
#pragma unroll
    for (int it = 0; it < 16; it++) {
        int u = tid + it * 256, tile = u >> 11, r = (u >> 4) & 127, c = u & 15;
        const __nv_bfloat16* src = (tile ? Qlo_g : Qhi_g) + (gq0 + r) * HDIM + c * 8;
        *(uint4*)(sm + tile * QTILE + r * STR + c * 16) = *(const uint4*)src;
    }
    kv_issue(smb + 2 * QTILE, b, 0, tid);
    CPC();

    // per-lane ldmatrix address pieces
    const int sub = l >> 3, l7 = l & 7;
    const uint32_t qoff = smb + (uint32_t)(w * 16 + l7 + (sub & 1) * 8) * STR + (l >> 4) * 16;
    const uint32_t koff = (uint32_t)((sub >> 1) * 8 + l7) * STR + (sub & 1) * 16;
    const uint32_t voff = (uint32_t)((sub & 1) * 8 + l7) * STR + (l >> 4) * 16;
    const int gl = l >> 2, tq = l & 3;
    const int rg0 = qt * 128 + w * 16 + gl;

    float o[16][4];
#pragma unroll
    for (int i = 0; i < 16; i++) o[i][0] = o[i][1] = o[i][2] = o[i][3] = 0.f;
    float la0 = 0.f, la1 = 0.f;

    for (int kt = 0; kt < nsteps; kt++) {
        const int t0 = kt * 64;
        const uint32_t kvb = smb + 2 * QTILE + (uint32_t)(kt & 1) * KVBUF;
        if (kt + 1 < nsteps) {
            kv_issue(smb + 2 * QTILE + (uint32_t)((kt + 1) & 1) * KVBUF, b, t0 + 64, tid);
            CPC();
            asm volatile("cp.async.wait_group 1;");
        } else {
            asm volatile("cp.async.wait_group 0;");
        }
        __syncthreads();

        // ---- S = Q K^T (3-split) ----
        float s[8][4];
#pragma unroll
        for (int i = 0; i < 8; i++) s[i][0] = s[i][1] = s[i][2] = s[i][3] = 0.f;
#pragma unroll
        for (int kc = 0; kc < 8; kc++) {
            uint32_t qh[4], ql[4];
            LDSM4(qh, qoff + kc * 32);
            LDSM4(ql, qoff + QTILE + kc * 32);
#pragma unroll
            for (int g = 0; g < 4; g++) {
                uint32_t kh[4], kl[4];
                uint32_t ka = kvb + koff + g * (16 * STR) + kc * 32;
                LDSM4(kh, ka);
                LDSM4(kl, ka + SUB);
                MMA(s[2 * g], qh, kh);     MMA(s[2 * g], qh, kl);     MMA(s[2 * g], ql, kh);
                MMA(s[2 * g + 1], qh, kh + 2); MMA(s[2 * g + 1], qh, kl + 2); MMA(s[2 * g + 1], ql, kh + 2);
            }
        }

        // ---- softmax (no max-sub) + P frag build ----
        const bool msk = (kt >= 2 * qt);
        uint32_t phi[4][4], plo[4][4];
#pragma unroll
        for (int nt = 0; nt < 8; nt++) {
            int col = t0 + nt * 8 + tq * 2;
            float e0 = fexp(s[nt][0]), e1 = fexp(s[nt][1]);
            float e2 = fexp(s[nt][2]), e3 = fexp(s[nt][3]);
            if (msk) {
                if (col > rg0) e0 = 0.f;
                if (col + 1 > rg0) e1 = 0.f;
                if (col > rg0 + 8) e2 = 0.f;
                if (col + 1 > rg0 + 8) e3 = 0.f;
            }
            la0 += e0 + e1;
            la1 += e2 + e3;
            __nv_bfloat16 h0, l0, h1, l1, h2, l2, h3, l3;
            splitf(e0, h0, l0); splitf(e1, h1, l1);
            splitf(e2, h2, l2); splitf(e3, h3, l3);
            phi[nt >> 1][(nt & 1) * 2 + 0] = b2u(h0, h1);
            phi[nt >> 1][(nt & 1) * 2 + 1] = b2u(h2, h3);
            plo[nt >> 1][(nt & 1) * 2 + 0] = b2u(l0, l1);
            plo[nt >> 1][(nt & 1) * 2 + 1] = b2u(l2, l3);
        }

        // ---- O += P V (3-split) ----
        const uint32_t vhb = kvb + 2 * SUB;
#pragma unroll
        for (int kc2 = 0; kc2 < 4; kc2++) {
#pragma unroll
            for (int nh = 0; nh < 8; nh++) {
                uint32_t vh[4], vl[4];
                uint32_t va = vhb + voff + kc2 * (16 * STR) + nh * 32;
                LDSM4T(vh, va);
                LDSM4T(vl, va + SUB);
                MMA(o[2 * nh], phi[kc2], vh);     MMA(o[2 * nh], phi[kc2], vl);
                MMA(o[2 * nh], plo[kc2], vh);
                MMA(o[2 * nh + 1], phi[kc2], vh + 2); MMA(o[2 * nh + 1], phi[kc2], vl + 2);
                MMA(o[2 * nh + 1], plo[kc2], vh + 2);
            }
        }
        __syncthreads();   // smem consumed before next step's cp.async overwrites
    }

    // ---- epilogue ----
    la0 += __shfl_xor_sync(0xffffffffu, la0, 1);
    la0 += __shfl_xor_sync(0xffffffffu, la0, 2);
    la1 += __shfl_xor_sync(0xffffffffu, la1, 1);
    la1 += __shfl_xor_sync(0xffffffffu, la1, 2);
    const float rl0 = 1.f / la0, rl1 = 1.f / la1;
    float* o0 = Out + (gq0 + w * 16 + gl) * HDIM + tq * 2;
    float* o1 = o0 + 8 * HDIM;
#pragma unroll
    for (int nt2 = 0; nt2 < 16; nt2++) {
        *(float2*)(o0 + nt2 * 8) = make_float2(o[nt2][0] * rl0, o[nt2][1] * rl0);
        *(float2*)(o1 + nt2 * 8) = make_float2(o[nt2][2] * rl1, o[nt2][3] * rl1);
    }
}

// ---------------------------------------------------------------------------
extern "C" void kernel_launch(void* const* d_in, const int* in_sizes, int n_in,
                              void* d_out, int out_size) {
    const float* x  = (const float*)d_in[0];
    const float* Wq = (const float*)d_in[1];
    const float* Wk = (const float*)d_in[2];
    const float* Wv = (const float*)d_in[3];
    float* out = (float*)d_out;
    (void)in_sizes; (void)n_in; (void)out_size;

    proj_gemm<<<dim3(MTOT / 128, 3), 256>>>(x, Wq, Wk, Wv);

    cudaFuncSetAttribute(flash_mma, cudaFuncAttributeMaxDynamicSharedMemorySize, SM_TOT);
    flash_mma<<<dim3(32, BSZ), 256, SM_TOT>>>(out);
}

// round 6
// speedup vs baseline: 2.6557x; 1.7685x over previous
#include <cuda_runtime.h>
#include <cuda_bf16.h>
#include <stdint.h>

#define BSZ   8
#define TLEN  4096
#define EDIM  1024
#define HDIM  128
#define MTOT  (BSZ * TLEN)

// bf16 hi/lo operands, all row-major [t][h].
__device__ __nv_bfloat16 Qhi_g[MTOT * HDIM], Qlo_g[MTOT * HDIM];
__device__ __nv_bfloat16 Khi_g[MTOT * HDIM], Klo_g[MTOT * HDIM];
__device__ __nv_bfloat16 Vhi_g[MTOT * HDIM], Vlo_g[MTOT * HDIM];
// pre-split weights [which][k][n]
__device__ __nv_bfloat16 Whi_g[3 * EDIM * HDIM], Wlo_g[3 * EDIM * HDIM];

// ---------------- helpers ----------------
__device__ __forceinline__ uint32_t smem_to_u32(const void* p) {
    uint32_t a;
    asm("{ .reg .u64 t; cvta.to.shared.u64 t, %1; cvt.u32.u64 %0, t; }" : "=r"(a) : "l"(p));
    return a;
}
#define LDSM4(R, A) asm volatile( \
    "ldmatrix.sync.aligned.m8n8.x4.shared.b16 {%0,%1,%2,%3}, [%4];" \
    : "=r"((R)[0]), "=r"((R)[1]), "=r"((R)[2]), "=r"((R)[3]) : "r"(A))
#define LDSM4T(R, A) asm volatile( \
    "ldmatrix.sync.aligned.m8n8.x4.trans.shared.b16 {%0,%1,%2,%3}, [%4];" \
    : "=r"((R)[0]), "=r"((R)[1]), "=r"((R)[2]), "=r"((R)[3]) : "r"(A))
#define MMA(C, A, B) asm volatile( \
    "mma.sync.aligned.m16n8k16.row.col.f32.bf16.bf16.f32 " \
    "{%0,%1,%2,%3},{%4,%5,%6,%7},{%8,%9},{%0,%1,%2,%3};" \
    : "+f"((C)[0]), "+f"((C)[1]), "+f"((C)[2]), "+f"((C)[3]) \
    : "r"((A)[0]), "r"((A)[1]), "r"((A)[2]), "r"((A)[3]), "r"((B)[0]), "r"((B)[1]))
#define CPA(S, G) asm volatile("cp.async.cg.shared.global [%0], [%1], 16;" \
    :: "r"(S), "l"(G))
#define CPC() asm volatile("cp.async.commit_group;")

__device__ __forceinline__ float fexp(float x) {      // FMA-pipe exp, ~2e-6 rel
    float t = x * 1.4426950408889634f;
    float k = rintf(t);
    float u = (t - k) * 0.6931471805599453f;
    float p = 1.f + u * (1.f + u * (0.5f + u * (0.16666667f +
              u * (0.041666667f + u * 0.0083333333f))));
    return p * __int_as_float(((int)k + 127) << 23);
}
__device__ __forceinline__ uint32_t b2u(__nv_bfloat16 a, __nv_bfloat16 b) {
    __nv_bfloat162 t; t.x = a; t.y = b; return *(uint32_t*)&t;
}
__device__ __forceinline__ void splitf(float f, __nv_bfloat16& h, __nv_bfloat16& l) {
    h = __float2bfloat16(f);
    l = __float2bfloat16(f - __bfloat162float(h));
}

// ---------------------------------------------------------------------------
// Kernel 0: split W into bf16 hi/lo. 96 blocks x 512 thr x 8 elems = 393216.
// ---------------------------------------------------------------------------
__global__ __launch_bounds__(512) void split_w(const float* __restrict__ Wq,
                                               const float* __restrict__ Wk,
                                               const float* __restrict__ Wv) {
    int t = blockIdx.x * 512 + threadIdx.x;
    int base = t * 8;
    int which = base >> 17;                       // 131072 per matrix
    const float* s = ((which == 0) ? Wq : (which == 1) ? Wk : Wv) + (base & 131071);
    float4 a = *(const float4*)s, b = *(const float4*)(s + 4);
    float f[8] = {a.x, a.y, a.z, a.w, b.x, b.y, b.z, b.w};
    uint32_t hp[4], lp[4];
#pragma unroll
    for (int i = 0; i < 4; i++) {
        __nv_bfloat16 h0, l0, h1, l1;
        splitf(f[2 * i], h0, l0);
        splitf(f[2 * i + 1], h1, l1);
        hp[i] = b2u(h0, h1);
        lp[i] = b2u(l0, l1);
    }
    *(uint4*)(Whi_g + base) = make_uint4(hp[0], hp[1], hp[2], hp[3]);
    *(uint4*)(Wlo_g + base) = make_uint4(lp[0], lp[1], lp[2], lp[3]);
}

// ---------------------------------------------------------------------------
// Kernel 1: projection via mma.sync bf16 3-split.
// grid (256, 3): which = 0 Q (scaled), 1 K, 2 V. BM=128, BN=128, BK=64.
// ---------------------------------------------------------------------------
#define PA_STR 144
#define PB_STR 272
#define PA_TILE (128 * PA_STR)          // 18432
#define PB_TILE (64 * PB_STR)           // 17408
#define PSM_TOT (2 * PA_TILE + 2 * PB_TILE)   // 71680

__global__ __launch_bounds__(256, 2) void proj_mma(const float* __restrict__ X) {
    extern __shared__ char psm[];
    const int which = blockIdx.y;
    const int m0 = blockIdx.x * 128, tid = threadIdx.x;
    const int w = tid >> 5, l = tid & 31;
    const int sub = l >> 3, l7 = l & 7;
    const uint32_t smb = smem_to_u32(psm);
    const uint32_t A_hi = smb, A_lo = smb + PA_TILE;
    const uint32_t B_hi = smb + 2 * PA_TILE, B_lo = B_hi + PB_TILE;

    const uint32_t aoff = (uint32_t)(w * 16 + l7 + (sub & 1) * 8) * PA_STR + (l >> 4) * 16;
    const uint32_t boff = (uint32_t)((sub & 1) * 8 + l7) * PB_STR + (l >> 4) * 16;

    const __nv_bfloat16* wh = Whi_g + which * 131072;
    const __nv_bfloat16* wl = Wlo_g + which * 131072;

    float acc[16][4];
#pragma unroll
    for (int i = 0; i < 16; i++) acc[i][0] = acc[i][1] = acc[i][2] = acc[i][3] = 0.f;
    float4 xa[8];

    // prologue: x regs + W cp.async for step 0
#pragma unroll
    for (int i = 0; i < 8; i++) {
        int idx = tid + i * 256, r = idx >> 4, c4 = idx & 15;
        xa[i] = *(const float4*)(X + (size_t)(m0 + r) * EDIM + c4 * 4);
    }
#pragma unroll
    for (int i = 0; i < 4; i++) {
        int idx = tid + i * 256, r = idx >> 4, c = idx & 15;
        CPA(B_hi + r * PB_STR + c * 16, wh + r * HDIM + c * 8);
        CPA(B_lo + r * PB_STR + c * 16, wl + r * HDIM + c * 8);
    }
    CPC();

    for (int s = 0; s < 16; s++) {
        // store x split (A tiles)
#pragma unroll
        for (int i = 0; i < 8; i++) {
            int idx = tid + i * 256, r = idx >> 4, c4 = idx & 15;
            __nv_bfloat16 h0, l0, h1, l1, h2, l2, h3, l3;
            splitf(xa[i].x, h0, l0); splitf(xa[i].y, h1, l1);
            splitf(xa[i].z, h2, l2); splitf(xa[i].w, h3, l3);
            uint32_t o = r * PA_STR + c4 * 8;
            *(uint2*)(psm + o)           = make_uint2(b2u(h0, h1), b2u(h2, h3));
            *(uint2*)(psm + PA_TILE + o) = make_uint2(b2u(l0, l1), b2u(l2, l3));
        }
        asm volatile("cp.async.wait_group 0;");
        __syncthreads();

        // prefetch next x tile into regs (overlaps MMA)
        if (s < 15) {
            int k0n = (s + 1) * 64;
#pragma unroll
            for (int i = 0; i < 8; i++) {
                int idx = tid + i * 256, r = idx >> 4, c4 = idx & 15;
                xa[i] = *(const float4*)(X + (size_t)(m0 + r) * EDIM + k0n + c4 * 4);
            }
        }

#pragma unroll
        for (int kc = 0; kc < 4; kc++) {
            uint32_t ah[4], al[4];
            LDSM4(ah, A_hi + aoff + kc * 32);
            LDSM4(al, A_lo + aoff + kc * 32);
#pragma unroll
            for (int ng = 0; ng < 8; ng++) {
                uint32_t bh[4], bl[4];
                uint32_t ba = B_hi + boff + kc * (16 * PB_STR) + ng * 32;
                LDSM4T(bh, ba);
                LDSM4T(bl, ba + PB_TILE);
                MMA(acc[2 * ng], ah, bh);     MMA(acc[2 * ng], ah, bl);
                MMA(acc[2 * ng], al, bh);
                MMA(acc[2 * ng + 1], ah, bh + 2); MMA(acc[2 * ng + 1], ah, bl + 2);
                MMA(acc[2 * ng + 1], al, bh + 2);
            }
        }
        __syncthreads();

        // issue next W tile (single buffer: safe after sync)
        if (s < 15) {
            const __nv_bfloat16* whn = wh + (size_t)(s + 1) * 64 * HDIM;
            const __nv_bfloat16* wln = wl + (size_t)(s + 1) * 64 * HDIM;
#pragma unroll
            for (int i = 0; i < 4; i++) {
                int idx = tid + i * 256, r = idx >> 4, c = idx & 15;
                CPA(B_hi + r * PB_STR + c * 16, whn + r * HDIM + c * 8);
                CPA(B_lo + r * PB_STR + c * 16, wln + r * HDIM + c * 8);
            }
            CPC();
        }
    }

    // epilogue: split-write bf16 hi/lo
    const float sc = (which == 0) ? 0.08838834764831845f : 1.f;
    __nv_bfloat16* dh = (which == 0) ? Qhi_g : (which == 1) ? Khi_g : Vhi_g;
    __nv_bfloat16* dl = (which == 0) ? Qlo_g : (which == 1) ? Klo_g : Vlo_g;
    const int gl = l >> 2, tq = l & 3;
    const size_t r0 = (size_t)m0 + w * 16 + gl;
#pragma unroll
    for (int t = 0; t < 16; t++) {
        int col = t * 8 + tq * 2;
        __nv_bfloat16 h0, l0, h1, l1;
        splitf(acc[t][0] * sc, h0, l0); splitf(acc[t][1] * sc, h1, l1);
        *(uint32_t*)(dh + r0 * HDIM + col) = b2u(h0, h1);
        *(uint32_t*)(dl + r0 * HDIM + col) = b2u(l0, l1);
        splitf(acc[t][2] * sc, h0, l0); splitf(acc[t][3] * sc, h1, l1);
        *(uint32_t*)(dh + (r0 + 8) * HDIM + col) = b2u(h0, h1);
        *(uint32_t*)(dl + (r0 + 8) * HDIM + col) = b2u(l0, l1);
    }
}

// ---------------------------------------------------------------------------
// Kernel 2: FA2-style mma.sync flash (unchanged from R5 win).
// ---------------------------------------------------------------------------
#define STR   272
#define QTILE 34816u
#define SUB   17408u
#define KVBUF (4 * SUB)
#define SM_TOT (2 * QTILE + 2 * KVBUF)

__device__ __forceinline__ void kv_issue(uint32_t dstb, int b, int t0, int tid) {
    const __nv_bfloat16* srcs[4] = {Khi_g, Klo_g, Vhi_g, Vlo_g};
#pragma unroll
    for (int sub = 0; sub < 4; sub++) {
        const __nv_bfloat16* sp = srcs[sub] + ((size_t)b * TLEN + t0) * HDIM;
#pragma unroll
        for (int i = 0; i < 4; i++) {
            int u = tid + i * 256, r = u >> 4, c = u & 15;
            CPA(dstb + sub * SUB + r * STR + c * 16, sp + r * HDIM + c * 8);
        }
    }
}

__global__ __launch_bounds__(256, 1) void flash_mma(float* __restrict__ Out) {
    extern __shared__ char sm[];
    const uint32_t smb = smem_to_u32(sm);
    const int tid = threadIdx.x, w = tid >> 5, l = tid & 31;
    const int qt = 31 - blockIdx.x, b = blockIdx.y;
    const size_t gq0 = (size_t)b * TLEN + (size_t)qt * 128;
    const int nsteps = 2 * qt + 2;

#pragma unroll
    for (int it = 0; it < 16; it++) {
        int u = tid + it * 256, tile = u >> 11, r = (u >> 4) & 127, c = u & 15;
        const __nv_bfloat16* src = (tile ? Qlo_g : Qhi_g) + (gq0 + r) * HDIM + c * 8;
        *(uint4*)(sm + tile * QTILE + r * STR + c * 16) = *(const uint4*)src;
    }
    kv_issue(smb + 2 * QTILE, b, 0, tid);
    CPC();

    const int sub = l >> 3, l7 = l & 7;
    const uint32_t qoff = smb + (uint32_t)(w * 16 + l7 + (sub & 1) * 8) * STR + (l >> 4) * 16;
    const uint32_t koff = (uint32_t)((sub >> 1) * 8 + l7) * STR + (sub & 1) * 16;
    const uint32_t voff = (uint32_t)((sub & 1) * 8 + l7) * STR + (l >> 4) * 16;
    const int gl = l >> 2, tq = l & 3;
    const int rg0 = qt * 128 + w * 16 + gl;

    float o[16][4];
#pragma unroll
    for (int i = 0; i < 16; i++) o[i][0] = o[i][1] = o[i][2] = o[i][3] = 0.f;
    float la0 = 0.f, la1 = 0.f;

    for (int kt = 0; kt < nsteps; kt++) {
        const int t0 = kt * 64;
        const uint32_t kvb = smb + 2 * QTILE + (uint32_t)(kt & 1) * KVBUF;
        if (kt + 1 < nsteps) {
            kv_issue(smb + 2 * QTILE + (uint32_t)((kt + 1) & 1) * KVBUF, b, t0 + 64, tid);
            CPC();
            asm volatile("cp.async.wait_group 1;");
        } else {
            asm volatile("cp.async.wait_group 0;");
        }
        __syncthreads();

        float s[8][4];
#pragma unroll
        for (int i = 0; i < 8; i++) s[i][0] = s[i][1] = s[i][2] = s[i][3] = 0.f;
#pragma unroll
        for (int kc = 0; kc < 8; kc++) {
            uint32_t qh[4], ql[4];
            LDSM4(qh, qoff + kc * 32);
            LDSM4(ql, qoff + QTILE + kc * 32);
#pragma unroll
            for (int g = 0; g < 4; g++) {
                uint32_t kh[4], kl[4];
                uint32_t ka = kvb + koff + g * (16 * STR) + kc * 32;
                LDSM4(kh, ka);
                LDSM4(kl, ka + SUB);
                MMA(s[2 * g], qh, kh);     MMA(s[2 * g], qh, kl);     MMA(s[2 * g], ql, kh);
                MMA(s[2 * g + 1], qh, kh + 2); MMA(s[2 * g + 1], qh, kl + 2); MMA(s[2 * g + 1], ql, kh + 2);
            }
        }

        const bool msk = (kt >= 2 * qt);
        uint32_t phi[4][4], plo[4][4];
#pragma unroll
        for (int nt = 0; nt < 8; nt++) {
            int col = t0 + nt * 8 + tq * 2;
            float e0 = fexp(s[nt][0]), e1 = fexp(s[nt][1]);
            float e2 = fexp(s[nt][2]), e3 = fexp(s[nt][3]);
            if (msk) {
                if (col > rg0) e0 = 0.f;
                if (col + 1 > rg0) e1 = 0.f;
                if (col > rg0 + 8) e2 = 0.f;
                if (col + 1 > rg0 + 8) e3 = 0.f;
            }
            la0 += e0 + e1;
            la1 += e2 + e3;
            __nv_bfloat16 h0, l0, h1, l1, h2, l2, h3, l3;
            splitf(e0, h0, l0); splitf(e1, h1, l1);
            splitf(e2, h2, l2); splitf(e3, h3, l3);
            phi[nt >> 1][(nt & 1) * 2 + 0] = b2u(h0, h1);
            phi[nt >> 1][(nt & 1) * 2 + 1] = b2u(h2, h3);
            plo[nt >> 1][(nt & 1) * 2 + 0] = b2u(l0, l1);
            plo[nt >> 1][(nt & 1) * 2 + 1] = b2u(l2, l3);
        }

        const uint32_t vhb = kvb + 2 * SUB;
#pragma unroll
        for (int kc2 = 0; kc2 < 4; kc2++) {
#pragma unroll
            for (int nh = 0; nh < 8; nh++) {
                uint32_t vh[4], vl[4];
                uint32_t va = vhb + voff + kc2 * (16 * STR) + nh * 32;
                LDSM4T(vh, va);
                LDSM4T(vl, va + SUB);
                MMA(o[2 * nh], phi[kc2], vh);     MMA(o[2 * nh], phi[kc2], vl);
                MMA(o[2 * nh], plo[kc2], vh);
                MMA(o[2 * nh + 1], phi[kc2], vh + 2); MMA(o[2 * nh + 1], phi[kc2], vl + 2);
                MMA(o[2 * nh + 1], plo[kc2], vh + 2);
            }
        }
        __syncthreads();
    }

    la0 += __shfl_xor_sync(0xffffffffu, la0, 1);
    la0 += __shfl_xor_sync(0xffffffffu, la0, 2);
    la1 += __shfl_xor_sync(0xffffffffu, la1, 1);
    la1 += __shfl_xor_sync(0xffffffffu, la1, 2);
    const float rl0 = 1.f / la0, rl1 = 1.f / la1;
    float* o0 = Out + (gq0 + w * 16 + gl) * HDIM + tq * 2;
    float* o1 = o0 + 8 * HDIM;
#pragma unroll
    for (int nt2 = 0; nt2 < 16; nt2++) {
        *(float2*)(o0 + nt2 * 8) = make_float2(o[nt2][0] * rl0, o[nt2][1] * rl0);
        *(float2*)(o1 + nt2 * 8) = make_float2(o[nt2][2] * rl1, o[nt2][3] * rl1);
    }
}

// ---------------------------------------------------------------------------
extern "C" void kernel_launch(void* const* d_in, const int* in_sizes, int n_in,
                              void* d_out, int out_size) {
    const float* x  = (const float*)d_in[0];
    const float* Wq = (const float*)d_in[1];
    const float* Wk = (const float*)d_in[2];
    const float* Wv = (const float*)d_in[3];
    float* out = (float*)d_out;
    (void)in_sizes; (void)n_in; (void)out_size;

    split_w<<<96, 512>>>(Wq, Wk, Wv);

    cudaFuncSetAttribute(proj_mma, cudaFuncAttributeMaxDynamicSharedMemorySize, PSM_TOT);
    proj_mma<<<dim3(256, 3), 256, PSM_TOT>>>(x);

    cudaFuncSetAttribute(flash_mma, cudaFuncAttributeMaxDynamicSharedMemorySize, SM_TOT);
    flash_mma<<<dim3(32, BSZ), 256, SM_TOT>>>(out);
}

// round 7
// speedup vs baseline: 2.7856x; 1.0489x over previous
#include <cuda_runtime.h>
#include <cuda_bf16.h>
#include <stdint.h>

#define BSZ   8
#define TLEN  4096
#define EDIM  1024
#define HDIM  128
#define MTOT  (BSZ * TLEN)

// bf16 hi/lo operands, all row-major [t][h].
__device__ __nv_bfloat16 Qhi_g[MTOT * HDIM], Qlo_g[MTOT * HDIM];
__device__ __nv_bfloat16 Khi_g[MTOT * HDIM], Klo_g[MTOT * HDIM];
__device__ __nv_bfloat16 Vhi_g[MTOT * HDIM], Vlo_g[MTOT * HDIM];
// pre-split weights [which][k][n]
__device__ __nv_bfloat16 Whi_g[3 * EDIM * HDIM], Wlo_g[3 * EDIM * HDIM];

// ---------------- helpers ----------------
__device__ __forceinline__ uint32_t smem_to_u32(const void* p) {
    uint32_t a;
    asm("{ .reg .u64 t; cvta.to.shared.u64 t, %1; cvt.u32.u64 %0, t; }" : "=r"(a) : "l"(p));
    return a;
}
#define LDSM4(R, A) asm volatile( \
    "ldmatrix.sync.aligned.m8n8.x4.shared.b16 {%0,%1,%2,%3}, [%4];" \
    : "=r"((R)[0]), "=r"((R)[1]), "=r"((R)[2]), "=r"((R)[3]) : "r"(A))
#define LDSM4T(R, A) asm volatile( \
    "ldmatrix.sync.aligned.m8n8.x4.trans.shared.b16 {%0,%1,%2,%3}, [%4];" \
    : "=r"((R)[0]), "=r"((R)[1]), "=r"((R)[2]), "=r"((R)[3]) : "r"(A))
#define MMA(C, A, B) asm volatile( \
    "mma.sync.aligned.m16n8k16.row.col.f32.bf16.bf16.f32 " \
    "{%0,%1,%2,%3},{%4,%5,%6,%7},{%8,%9},{%0,%1,%2,%3};" \
    : "+f"((C)[0]), "+f"((C)[1]), "+f"((C)[2]), "+f"((C)[3]) \
    : "r"((A)[0]), "r"((A)[1]), "r"((A)[2]), "r"((A)[3]), "r"((B)[0]), "r"((B)[1]))
#define CPA(S, G) asm volatile("cp.async.cg.shared.global [%0], [%1], 16;" \
    :: "r"(S), "l"(G))
#define CPC() asm volatile("cp.async.commit_group;")

__device__ __forceinline__ float fexp(float x) {      // FMA-pipe exp, ~2e-6 rel
    float t = x * 1.4426950408889634f;
    float k = rintf(t);
    float u = (t - k) * 0.6931471805599453f;
    float p = 1.f + u * (1.f + u * (0.5f + u * (0.16666667f +
              u * (0.041666667f + u * 0.0083333333f))));
    return p * __int_as_float(((int)k + 127) << 23);
}
__device__ __forceinline__ uint32_t b2u(__nv_bfloat16 a, __nv_bfloat16 b) {
    __nv_bfloat162 t; t.x = a; t.y = b; return *(uint32_t*)&t;
}
__device__ __forceinline__ void splitf(float f, __nv_bfloat16& h, __nv_bfloat16& l) {
    h = __float2bfloat16(f);
    l = __float2bfloat16(f - __bfloat162float(h));
}

// ---------------------------------------------------------------------------
// Kernel 0: split W into bf16 hi/lo.
// ---------------------------------------------------------------------------
__global__ __launch_bounds__(512) void split_w(const float* __restrict__ Wq,
                                               const float* __restrict__ Wk,
                                               const float* __restrict__ Wv) {
    int t = blockIdx.x * 512 + threadIdx.x;
    int base = t * 8;
    int which = base >> 17;
    const float* s = ((which == 0) ? Wq : (which == 1) ? Wk : Wv) + (base & 131071);
    float4 a = *(const float4*)s, b = *(const float4*)(s + 4);
    float f[8] = {a.x, a.y, a.z, a.w, b.x, b.y, b.z, b.w};
    uint32_t hp[4], lp[4];
#pragma unroll
    for (int i = 0; i < 4; i++) {
        __nv_bfloat16 h0, l0, h1, l1;
        splitf(f[2 * i], h0, l0);
        splitf(f[2 * i + 1], h1, l1);
        hp[i] = b2u(h0, h1);
        lp[i] = b2u(l0, l1);
    }
    *(uint4*)(Whi_g + base) = make_uint4(hp[0], hp[1], hp[2], hp[3]);
    *(uint4*)(Wlo_g + base) = make_uint4(lp[0], lp[1], lp[2], lp[3]);
}

// ---------------------------------------------------------------------------
// Kernel 1: projection via mma.sync bf16 3-split (unchanged from R6 win).
// ---------------------------------------------------------------------------
#define PA_STR 144
#define PB_STR 272
#define PA_TILE (128 * PA_STR)
#define PB_TILE (64 * PB_STR)
#define PSM_TOT (2 * PA_TILE + 2 * PB_TILE)

__global__ __launch_bounds__(256, 2) void proj_mma(const float* __restrict__ X) {
    extern __shared__ char psm[];
    const int which = blockIdx.y;
    const int m0 = blockIdx.x * 128, tid = threadIdx.x;
    const int w = tid >> 5, l = tid & 31;
    const int sub = l >> 3, l7 = l & 7;
    const uint32_t smb = smem_to_u32(psm);
    const uint32_t A_hi = smb, A_lo = smb + PA_TILE;
    const uint32_t B_hi = smb + 2 * PA_TILE, B_lo = B_hi + PB_TILE;

    const uint32_t aoff = (uint32_t)(w * 16 + l7 + (sub & 1) * 8) * PA_STR + (l >> 4) * 16;
    const uint32_t boff = (uint32_t)((sub & 1) * 8 + l7) * PB_STR + (l >> 4) * 16;

    const __nv_bfloat16* wh = Whi_g + which * 131072;
    const __nv_bfloat16* wl = Wlo_g + which * 131072;

    float acc[16][4];
#pragma unroll
    for (int i = 0; i < 16; i++) acc[i][0] = acc[i][1] = acc[i][2] = acc[i][3] = 0.f;
    float4 xa[8];

#pragma unroll
    for (int i = 0; i < 8; i++) {
        int idx = tid + i * 256, r = idx >> 4, c4 = idx & 15;
        xa[i] = *(const float4*)(X + (size_t)(m0 + r) * EDIM + c4 * 4);
    }
#pragma unroll
    for (int i = 0; i < 4; i++) {
        int idx = tid + i * 256, r = idx >> 4, c = idx & 15;
        CPA(B_hi + r * PB_STR + c * 16, wh + r * HDIM + c * 8);
        CPA(B_lo + r * PB_STR + c * 16, wl + r * HDIM + c * 8);
    }
    CPC();

    for (int s = 0; s < 16; s++) {
#pragma unroll
        for (int i = 0; i < 8; i++) {
            int idx = tid + i * 256, r = idx >> 4, c4 = idx & 15;
            __nv_bfloat16 h0, l0, h1, l1, h2, l2, h3, l3;
            splitf(xa[i].x, h0, l0); splitf(xa[i].y, h1, l1);
            splitf(xa[i].z, h2, l2); splitf(xa[i].w, h3, l3);
            uint32_t o = r * PA_STR + c4 * 8;
            *(uint2*)(psm + o)           = make_uint2(b2u(h0, h1), b2u(h2, h3));
            *(uint2*)(psm + PA_TILE + o) = make_uint2(b2u(l0, l1), b2u(l2, l3));
        }
        asm volatile("cp.async.wait_group 0;");
        __syncthreads();

        if (s < 15) {
            int k0n = (s + 1) * 64;
#pragma unroll
            for (int i = 0; i < 8; i++) {
                int idx = tid + i * 256, r = idx >> 4, c4 = idx & 15;
                xa[i] = *(const float4*)(X + (size_t)(m0 + r) * EDIM + k0n + c4 * 4);
            }
        }

#pragma unroll
        for (int kc = 0; kc < 4; kc++) {
            uint32_t ah[4], al[4];
            LDSM4(ah, A_hi + aoff + kc * 32);
            LDSM4(al, A_lo + aoff + kc * 32);
#pragma unroll
            for (int ng = 0; ng < 8; ng++) {
                uint32_t bh[4], bl[4];
                uint32_t ba = B_hi + boff + kc * (16 * PB_STR) + ng * 32;
                LDSM4T(bh, ba);
                LDSM4T(bl, ba + PB_TILE);
                MMA(acc[2 * ng], ah, bh);     MMA(acc[2 * ng], ah, bl);
                MMA(acc[2 * ng], al, bh);
                MMA(acc[2 * ng + 1], ah, bh + 2); MMA(acc[2 * ng + 1], ah, bl + 2);
                MMA(acc[2 * ng + 1], al, bh + 2);
            }
        }
        __syncthreads();

        if (s < 15) {
            const __nv_bfloat16* whn = wh + (size_t)(s + 1) * 64 * HDIM;
            const __nv_bfloat16* wln = wl + (size_t)(s + 1) * 64 * HDIM;
#pragma unroll
            for (int i = 0; i < 4; i++) {
                int idx = tid + i * 256, r = idx >> 4, c = idx & 15;
                CPA(B_hi + r * PB_STR + c * 16, whn + r * HDIM + c * 8);
                CPA(B_lo + r * PB_STR + c * 16, wln + r * HDIM + c * 8);
            }
            CPC();
        }
    }

    const float sc = (which == 0) ? 0.08838834764831845f : 1.f;
    __nv_bfloat16* dh = (which == 0) ? Qhi_g : (which == 1) ? Khi_g : Vhi_g;
    __nv_bfloat16* dl = (which == 0) ? Qlo_g : (which == 1) ? Klo_g : Vlo_g;
    const int gl = l >> 2, tq = l & 3;
    const size_t r0 = (size_t)m0 + w * 16 + gl;
#pragma unroll
    for (int t = 0; t < 16; t++) {
        int col = t * 8 + tq * 2;
        __nv_bfloat16 h0, l0, h1, l1;
        splitf(acc[t][0] * sc, h0, l0); splitf(acc[t][1] * sc, h1, l1);
        *(uint32_t*)(dh + r0 * HDIM + col) = b2u(h0, h1);
        *(uint32_t*)(dl + r0 * HDIM + col) = b2u(l0, l1);
        splitf(acc[t][2] * sc, h0, l0); splitf(acc[t][3] * sc, h1, l1);
        *(uint32_t*)(dh + (r0 + 8) * HDIM + col) = b2u(h0, h1);
        *(uint32_t*)(dl + (r0 + 8) * HDIM + col) = b2u(l0, l1);
    }
}

// ---------------------------------------------------------------------------
// Kernel 2: FA2-style mma.sync flash. Single barrier/step; exp interleaved
// with PV MMAs per P-chunk.
// ---------------------------------------------------------------------------
#define STR   272
#define QTILE 34816u
#define SUB   17408u
#define KVBUF (4 * SUB)
#define SM_TOT (2 * QTILE + 2 * KVBUF)

__device__ __forceinline__ void kv_issue(uint32_t dstb, int b, int t0, int tid) {
    const __nv_bfloat16* srcs[4] = {Khi_g, Klo_g, Vhi_g, Vlo_g};
#pragma unroll
    for (int sub = 0; sub < 4; sub++) {
        const __nv_bfloat16* sp = srcs[sub] + ((size_t)b * TLEN + t0) * HDIM;
#pragma unroll
        for (int i = 0; i < 4; i++) {
            int u = tid + i * 256, r = u >> 4, c = u & 15;
            CPA(dstb + sub * SUB + r * STR + c * 16, sp + r * HDIM + c * 8);
        }
    }
}

__global__ __launch_bounds__(256, 1) void flash_mma(float* __restrict__ Out) {
    extern __shared__ char sm[];
    const uint32_t smb = smem_to_u32(sm);
    const int tid = threadIdx.x, w = tid >> 5, l = tid & 31;
    const int qt = 31 - blockIdx.x, b = blockIdx.y;
    const size_t gq0 = (size_t)b * TLEN + (size_t)qt * 128;
    const int nsteps = 2 * qt + 2;

    // cp.async for first KV tile first (overlaps the Q fill below)
    kv_issue(smb + 2 * QTILE, b, 0, tid);
    CPC();

    // Q tile -> smem (hi, lo)
#pragma unroll
    for (int it = 0; it < 16; it++) {
        int u = tid + it * 256, tile = u >> 11, r = (u >> 4) & 127, c = u & 15;
        const __nv_bfloat16* src = (tile ? Qlo_g : Qhi_g) + (gq0 + r) * HDIM + c * 8;
        *(uint4*)(sm + tile * QTILE + r * STR + c * 16) = *(const uint4*)src;
    }

    const int sub = l >> 3, l7 = l & 7;
    const uint32_t qoff = smb + (uint32_t)(w * 16 + l7 + (sub & 1) * 8) * STR + (l >> 4) * 16;
    const uint32_t koff = (uint32_t)((sub >> 1) * 8 + l7) * STR + (sub & 1) * 16;
    const uint32_t voff = (uint32_t)((sub & 1) * 8 + l7) * STR + (l >> 4) * 16;
    const int gl = l >> 2, tq = l & 3;
    const int rg0 = qt * 128 + w * 16 + gl;

    float o[16][4];
#pragma unroll
    for (int i = 0; i < 16; i++) o[i][0] = o[i][1] = o[i][2] = o[i][3] = 0.f;
    float la0 = 0.f, la1 = 0.f;

    for (int kt = 0; kt < nsteps; kt++) {
        const int t0 = kt * 64;
        const uint32_t kvb = smb + 2 * QTILE + (uint32_t)(kt & 1) * KVBUF;

        // cp(kt) complete + all warps past step kt-1, then prefetch kt+1.
        asm volatile("cp.async.wait_group 0;");
        __syncthreads();
        if (kt + 1 < nsteps) {
            kv_issue(smb + 2 * QTILE + (uint32_t)((kt + 1) & 1) * KVBUF, b, t0 + 64, tid);
            CPC();
        }

        // ---- S = Q K^T (3-split) ----
        float s[8][4];
#pragma unroll
        for (int i = 0; i < 8; i++) s[i][0] = s[i][1] = s[i][2] = s[i][3] = 0.f;
#pragma unroll
        for (int kc = 0; kc < 8; kc++) {
            uint32_t qh[4], ql[4];
            LDSM4(qh, qoff + kc * 32);
            LDSM4(ql, qoff + QTILE + kc * 32);
#pragma unroll
            for (int g = 0; g < 4; g++) {
                uint32_t kh[4], kl[4];
                uint32_t ka = kvb + koff + g * (16 * STR) + kc * 32;
                LDSM4(kh, ka);
                LDSM4(kl, ka + SUB);
                MMA(s[2 * g], qh, kh);     MMA(s[2 * g], qh, kl);     MMA(s[2 * g], ql, kh);
                MMA(s[2 * g + 1], qh, kh + 2); MMA(s[2 * g + 1], qh, kl + 2); MMA(s[2 * g + 1], ql, kh + 2);
            }
        }

        // ---- softmax + PV interleaved per P-chunk (exp overlaps MMAs) ----
        const bool msk = (kt >= 2 * qt);
        const uint32_t vhb = kvb + 2 * SUB;
#pragma unroll
        for (int kc2 = 0; kc2 < 4; kc2++) {
            uint32_t phic[4], ploc[4];
#pragma unroll
            for (int h = 0; h < 2; h++) {
                const int nt = 2 * kc2 + h;
                int col = t0 + nt * 8 + tq * 2;
                float e0 = fexp(s[nt][0]), e1 = fexp(s[nt][1]);
                float e2 = fexp(s[nt][2]), e3 = fexp(s[nt][3]);
                if (msk) {
                    if (col > rg0) e0 = 0.f;
                    if (col + 1 > rg0) e1 = 0.f;
                    if (col > rg0 + 8) e2 = 0.f;
                    if (col + 1 > rg0 + 8) e3 = 0.f;
                }
                la0 += e0 + e1;
                la1 += e2 + e3;
                __nv_bfloat16 h0, l0, h1, l1, h2, l2, h3, l3;
                splitf(e0, h0, l0); splitf(e1, h1, l1);
                splitf(e2, h2, l2); splitf(e3, h3, l3);
                phic[h * 2 + 0] = b2u(h0, h1);
                phic[h * 2 + 1] = b2u(h2, h3);
                ploc[h * 2 + 0] = b2u(l0, l1);
                ploc[h * 2 + 1] = b2u(l2, l3);
            }
#pragma unroll
            for (int nh = 0; nh < 8; nh++) {
                uint32_t vh[4], vl[4];
                uint32_t va = vhb + voff + kc2 * (16 * STR) + nh * 32;
                LDSM4T(vh, va);
                LDSM4T(vl, va + SUB);
                MMA(o[2 * nh], phic, vh);     MMA(o[2 * nh], phic, vl);
                MMA(o[2 * nh], ploc, vh);
                MMA(o[2 * nh + 1], phic, vh + 2); MMA(o[2 * nh + 1], phic, vl + 2);
                MMA(o[2 * nh + 1], ploc, vh + 2);
            }
        }
        // no end-of-step barrier: next step's barrier protects buffer reuse
    }

    la0 += __shfl_xor_sync(0xffffffffu, la0, 1);
    la0 += __shfl_xor_sync(0xffffffffu, la0, 2);
    la1 += __shfl_xor_sync(0xffffffffu, la1, 1);
    la1 += __shfl_xor_sync(0xffffffffu, la1, 2);
    const float rl0 = 1.f / la0, rl1 = 1.f / la1;
    float* o0 = Out + (gq0 + w * 16 + gl) * HDIM + tq * 2;
    float* o1 = o0 + 8 * HDIM;
#pragma unroll
    for (int nt2 = 0; nt2 < 16; nt2++) {
        *(float2*)(o0 + nt2 * 8) = make_float2(o[nt2][0] * rl0, o[nt2][1] * rl0);
        *(float2*)(o1 + nt2 * 8) = make_float2(o[nt2][2] * rl1, o[nt2][3] * rl1);
    }
}

// ---------------------------------------------------------------------------
extern "C" void kernel_launch(void* const* d_in, const int* in_sizes, int n_in,
                              void* d_out, int out_size) {
    const float* x  = (const float*)d_in[0];
    const float* Wq = (const float*)d_in[1];
    const float* Wk = (const float*)d_in[2];
    const float* Wv = (const float*)d_in[3];
    float* out = (float*)d_out;
    (void)in_sizes; (void)n_in; (void)out_size;

    split_w<<<96, 512>>>(Wq, Wk, Wv);

    cudaFuncSetAttribute(proj_mma, cudaFuncAttributeMaxDynamicSharedMemorySize, PSM_TOT);
    proj_mma<<<dim3(256, 3), 256, PSM_TOT>>>(x);

    cudaFuncSetAttribute(flash_mma, cudaFuncAttributeMaxDynamicSharedMemorySize, SM_TOT);
    flash_mma<<<dim3(32, BSZ), 256, SM_TOT>>>(out);
}

// round 8
// speedup vs baseline: 3.4590x; 1.2417x over previous
#include <cuda_runtime.h>
#include <cuda_bf16.h>
#include <stdint.h>

#define BSZ   8
#define TLEN  4096
#define EDIM  1024
#define HDIM  128
#define MTOT  (BSZ * TLEN)

// bf16 hi/lo operands, all row-major [t][h].
__device__ __nv_bfloat16 Qhi_g[MTOT * HDIM], Qlo_g[MTOT * HDIM];
__device__ __nv_bfloat16 Khi_g[MTOT * HDIM], Klo_g[MTOT * HDIM];
__device__ __nv_bfloat16 Vhi_g[MTOT * HDIM], Vlo_g[MTOT * HDIM];
// pre-split weights [which][k][n]
__device__ __nv_bfloat16 Whi_g[3 * EDIM * HDIM], Wlo_g[3 * EDIM * HDIM];

// ---------------- helpers ----------------
__device__ __forceinline__ uint32_t smem_to_u32(const void* p) {
    uint32_t a;
    asm("{ .reg .u64 t; cvta.to.shared.u64 t, %1; cvt.u32.u64 %0, t; }" : "=r"(a) : "l"(p));
    return a;
}
#define LDSM4(R, A) asm volatile( \
    "ldmatrix.sync.aligned.m8n8.x4.shared.b16 {%0,%1,%2,%3}, [%4];" \
    : "=r"((R)[0]), "=r"((R)[1]), "=r"((R)[2]), "=r"((R)[3]) : "r"(A))
#define LDSM4T(R, A) asm volatile( \
    "ldmatrix.sync.aligned.m8n8.x4.trans.shared.b16 {%0,%1,%2,%3}, [%4];" \
    : "=r"((R)[0]), "=r"((R)[1]), "=r"((R)[2]), "=r"((R)[3]) : "r"(A))
#define MMA(C, A, B) asm volatile( \
    "mma.sync.aligned.m16n8k16.row.col.f32.bf16.bf16.f32 " \
    "{%0,%1,%2,%3},{%4,%5,%6,%7},{%8,%9},{%0,%1,%2,%3};" \
    : "+f"((C)[0]), "+f"((C)[1]), "+f"((C)[2]), "+f"((C)[3]) \
    : "r"((A)[0]), "r"((A)[1]), "r"((A)[2]), "r"((A)[3]), "r"((B)[0]), "r"((B)[1]))
#define CPA(S, G) asm volatile("cp.async.cg.shared.global [%0], [%1], 16;" \
    :: "r"(S), "l"(G))
#define CPC() asm volatile("cp.async.commit_group;")

__device__ __forceinline__ float fexp(float x) {      // FMA-pipe exp, ~2e-6 rel
    float t = x * 1.4426950408889634f;
    float k = rintf(t);
    float u = (t - k) * 0.6931471805599453f;
    float p = 1.f + u * (1.f + u * (0.5f + u * (0.16666667f +
              u * (0.041666667f + u * 0.0083333333f))));
    return p * __int_as_float(((int)k + 127) << 23);
}
__device__ __forceinline__ uint32_t b2u(__nv_bfloat16 a, __nv_bfloat16 b) {
    __nv_bfloat162 t; t.x = a; t.y = b; return *(uint32_t*)&t;
}
__device__ __forceinline__ void splitf(float f, __nv_bfloat16& h, __nv_bfloat16& l) {
    h = __float2bfloat16(f);
    l = __float2bfloat16(f - __bfloat162float(h));
}

// ---------------------------------------------------------------------------
// Kernel 0: split W into bf16 hi/lo.
// ---------------------------------------------------------------------------
__global__ __launch_bounds__(512) void split_w(const float* __restrict__ Wq,
                                               const float* __restrict__ Wk,
                                               const float* __restrict__ Wv) {
    int t = blockIdx.x * 512 + threadIdx.x;
    int base = t * 8;
    int which = base >> 17;
    const float* s = ((which == 0) ? Wq : (which == 1) ? Wk : Wv) + (base & 131071);
    float4 a = *(const float4*)s, b = *(const float4*)(s + 4);
    float f[8] = {a.x, a.y, a.z, a.w, b.x, b.y, b.z, b.w};
    uint32_t hp[4], lp[4];
#pragma unroll
    for (int i = 0; i < 4; i++) {
        __nv_bfloat16 h0, l0, h1, l1;
        splitf(f[2 * i], h0, l0);
        splitf(f[2 * i + 1], h1, l1);
        hp[i] = b2u(h0, h1);
        lp[i] = b2u(l0, l1);
    }
    *(uint4*)(Whi_g + base) = make_uint4(hp[0], hp[1], hp[2], hp[3]);
    *(uint4*)(Wlo_g + base) = make_uint4(lp[0], lp[1], lp[2], lp[3]);
}

// ---------------------------------------------------------------------------
// Kernel 1: projection via mma.sync bf16 3-split (unchanged — R6 win).
// ---------------------------------------------------------------------------
#define PA_STR 144
#define PB_STR 272
#define PA_TILE (128 * PA_STR)
#define PB_TILE (64 * PB_STR)
#define PSM_TOT (2 * PA_TILE + 2 * PB_TILE)

__global__ __launch_bounds__(256, 2) void proj_mma(const float* __restrict__ X) {
    extern __shared__ char psm[];
    const int which = blockIdx.y;
    const int m0 = blockIdx.x * 128, tid = threadIdx.x;
    const int w = tid >> 5, l = tid & 31;
    const int sub = l >> 3, l7 = l & 7;
    const uint32_t smb = smem_to_u32(psm);
    const uint32_t A_hi = smb, A_lo = smb + PA_TILE;
    const uint32_t B_hi = smb + 2 * PA_TILE, B_lo = B_hi + PB_TILE;

    const uint32_t aoff = (uint32_t)(w * 16 + l7 + (sub & 1) * 8) * PA_STR + (l >> 4) * 16;
    const uint32_t boff = (uint32_t)((sub & 1) * 8 + l7) * PB_STR + (l >> 4) * 16;

    const __nv_bfloat16* wh = Whi_g + which * 131072;
    const __nv_bfloat16* wl = Wlo_g + which * 131072;

    float acc[16][4];
#pragma unroll
    for (int i = 0; i < 16; i++) acc[i][0] = acc[i][1] = acc[i][2] = acc[i][3] = 0.f;
    float4 xa[8];

#pragma unroll
    for (int i = 0; i < 8; i++) {
        int idx = tid + i * 256, r = idx >> 4, c4 = idx & 15;
        xa[i] = *(const float4*)(X + (size_t)(m0 + r) * EDIM + c4 * 4);
    }
#pragma unroll
    for (int i = 0; i < 4; i++) {
        int idx = tid + i * 256, r = idx >> 4, c = idx & 15;
        CPA(B_hi + r * PB_STR + c * 16, wh + r * HDIM + c * 8);
        CPA(B_lo + r * PB_STR + c * 16, wl + r * HDIM + c * 8);
    }
    CPC();

    for (int s = 0; s < 16; s++) {
#pragma unroll
        for (int i = 0; i < 8; i++) {
            int idx = tid + i * 256, r = idx >> 4, c4 = idx & 15;
            __nv_bfloat16 h0, l0, h1, l1, h2, l2, h3, l3;
            splitf(xa[i].x, h0, l0); splitf(xa[i].y, h1, l1);
            splitf(xa[i].z, h2, l2); splitf(xa[i].w, h3, l3);
            uint32_t o = r * PA_STR + c4 * 8;
            *(uint2*)(psm + o)           = make_uint2(b2u(h0, h1), b2u(h2, h3));
            *(uint2*)(psm + PA_TILE + o) = make_uint2(b2u(l0, l1), b2u(l2, l3));
        }
        asm volatile("cp.async.wait_group 0;");
        __syncthreads();

        if (s < 15) {
            int k0n = (s + 1) * 64;
#pragma unroll
            for (int i = 0; i < 8; i++) {
                int idx = tid + i * 256, r = idx >> 4, c4 = idx & 15;
                xa[i] = *(const float4*)(X + (size_t)(m0 + r) * EDIM + k0n + c4 * 4);
            }
        }

#pragma unroll
        for (int kc = 0; kc < 4; kc++) {
            uint32_t ah[4], al[4];
            LDSM4(ah, A_hi + aoff + kc * 32);
            LDSM4(al, A_lo + aoff + kc * 32);
#pragma unroll
            for (int ng = 0; ng < 8; ng++) {
                uint32_t bh[4], bl[4];
                uint32_t ba = B_hi + boff + kc * (16 * PB_STR) + ng * 32;
                LDSM4T(bh, ba);
                LDSM4T(bl, ba + PB_TILE);
                MMA(acc[2 * ng], ah, bh);     MMA(acc[2 * ng], ah, bl);
                MMA(acc[2 * ng], al, bh);
                MMA(acc[2 * ng + 1], ah, bh + 2); MMA(acc[2 * ng + 1], ah, bl + 2);
                MMA(acc[2 * ng + 1], al, bh + 2);
            }
        }
        __syncthreads();

        if (s < 15) {
            const __nv_bfloat16* whn = wh + (size_t)(s + 1) * 64 * HDIM;
            const __nv_bfloat16* wln = wl + (size_t)(s + 1) * 64 * HDIM;
#pragma unroll
            for (int i = 0; i < 4; i++) {
                int idx = tid + i * 256, r = idx >> 4, c = idx & 15;
                CPA(B_hi + r * PB_STR + c * 16, whn + r * HDIM + c * 8);
                CPA(B_lo + r * PB_STR + c * 16, wln + r * HDIM + c * 8);
            }
            CPC();
        }
    }

    const float sc = (which == 0) ? 0.08838834764831845f : 1.f;
    __nv_bfloat16* dh = (which == 0) ? Qhi_g : (which == 1) ? Khi_g : Vhi_g;
    __nv_bfloat16* dl = (which == 0) ? Qlo_g : (which == 1) ? Klo_g : Vlo_g;
    const int gl = l >> 2, tq = l & 3;
    const size_t r0 = (size_t)m0 + w * 16 + gl;
#pragma unroll
    for (int t = 0; t < 16; t++) {
        int col = t * 8 + tq * 2;
        __nv_bfloat16 h0, l0, h1, l1;
        splitf(acc[t][0] * sc, h0, l0); splitf(acc[t][1] * sc, h1, l1);
        *(uint32_t*)(dh + r0 * HDIM + col) = b2u(h0, h1);
        *(uint32_t*)(dl + r0 * HDIM + col) = b2u(l0, l1);
        splitf(acc[t][2] * sc, h0, l0); splitf(acc[t][3] * sc, h1, l1);
        *(uint32_t*)(dh + (r0 + 8) * HDIM + col) = b2u(h0, h1);
        *(uint32_t*)(dl + (r0 + 8) * HDIM + col) = b2u(l0, l1);
    }
}

// ---------------------------------------------------------------------------
// Kernel 2: FA2-style mma.sync flash. Split-pass MMA ordering (8 independent
// MMAs between same-accumulator writes); heavy blocks first in linear bid.
// ---------------------------------------------------------------------------
#define STR   272
#define QTILE 34816u
#define SUB   17408u
#define KVBUF (4 * SUB)
#define SM_TOT (2 * QTILE + 2 * KVBUF)

__device__ __forceinline__ void kv_issue(uint32_t dstb, int b, int t0, int tid) {
    const __nv_bfloat16* srcs[4] = {Khi_g, Klo_g, Vhi_g, Vlo_g};
#pragma unroll
    for (int sub = 0; sub < 4; sub++) {
        const __nv_bfloat16* sp = srcs[sub] + ((size_t)b * TLEN + t0) * HDIM;
#pragma unroll
        for (int i = 0; i < 4; i++) {
            int u = tid + i * 256, r = u >> 4, c = u & 15;
            CPA(dstb + sub * SUB + r * STR + c * 16, sp + r * HDIM + c * 8);
        }
    }
}

__global__ __launch_bounds__(256, 1) void flash_mma(float* __restrict__ Out) {
    extern __shared__ char sm[];
    const uint32_t smb = smem_to_u32(sm);
    const int tid = threadIdx.x, w = tid >> 5, l = tid & 31;
    // grid = (BSZ, 32): all eight qt=31 blocks are bids 0..7 -> first wave.
    const int qt = 31 - blockIdx.y, b = blockIdx.x;
    const size_t gq0 = (size_t)b * TLEN + (size_t)qt * 128;
    const int nsteps = 2 * qt + 2;

    kv_issue(smb + 2 * QTILE, b, 0, tid);
    CPC();

#pragma unroll
    for (int it = 0; it < 16; it++) {
        int u = tid + it * 256, tile = u >> 11, r = (u >> 4) & 127, c = u & 15;
        const __nv_bfloat16* src = (tile ? Qlo_g : Qhi_g) + (gq0 + r) * HDIM + c * 8;
        *(uint4*)(sm + tile * QTILE + r * STR + c * 16) = *(const uint4*)src;
    }

    const int sub = l >> 3, l7 = l & 7;
    const uint32_t qoff = smb + (uint32_t)(w * 16 + l7 + (sub & 1) * 8) * STR + (l >> 4) * 16;
    const uint32_t koff = (uint32_t)((sub >> 1) * 8 + l7) * STR + (sub & 1) * 16;
    const uint32_t voff = (uint32_t)((sub & 1) * 8 + l7) * STR + (l >> 4) * 16;
    const int gl = l >> 2, tq = l & 3;
    const int rg0 = qt * 128 + w * 16 + gl;

    float o[16][4];
#pragma unroll
    for (int i = 0; i < 16; i++) o[i][0] = o[i][1] = o[i][2] = o[i][3] = 0.f;
    float la0 = 0.f, la1 = 0.f;

    for (int kt = 0; kt < nsteps; kt++) {
        const int t0 = kt * 64;
        const uint32_t kvb = smb + 2 * QTILE + (uint32_t)(kt & 1) * KVBUF;

        asm volatile("cp.async.wait_group 0;");
        __syncthreads();
        if (kt + 1 < nsteps) {
            kv_issue(smb + 2 * QTILE + (uint32_t)((kt + 1) & 1) * KVBUF, b, t0 + 64, tid);
            CPC();
        }

        // ---- S = Q K^T : split-pass ordering, 8 indep MMAs per pass ----
        float s[8][4];
#pragma unroll
        for (int i = 0; i < 8; i++) s[i][0] = s[i][1] = s[i][2] = s[i][3] = 0.f;
#pragma unroll
        for (int kc = 0; kc < 8; kc++) {
            uint32_t qh[4], ql[4];
            LDSM4(qh, qoff + kc * 32);
            LDSM4(ql, qoff + QTILE + kc * 32);
            uint32_t kh[4][4], kl[4][4];
#pragma unroll
            for (int g = 0; g < 4; g++) {
                uint32_t ka = kvb + koff + g * (16 * STR) + kc * 32;
                LDSM4(kh[g], ka);
                LDSM4(kl[g], ka + SUB);
            }
#pragma unroll
            for (int g = 0; g < 4; g++) {           // pass 1: qh * khi
                MMA(s[2 * g], qh, kh[g]);
                MMA(s[2 * g + 1], qh, kh[g] + 2);
            }
#pragma unroll
            for (int g = 0; g < 4; g++) {           // pass 2: qh * klo
                MMA(s[2 * g], qh, kl[g]);
                MMA(s[2 * g + 1], qh, kl[g] + 2);
            }
#pragma unroll
            for (int g = 0; g < 4; g++) {           // pass 3: qlo * khi
                MMA(s[2 * g], ql, kh[g]);
                MMA(s[2 * g + 1], ql, kh[g] + 2);
            }
        }

        // ---- softmax + PV, split-pass ordering ----
        const bool msk = (kt >= 2 * qt);
        const uint32_t vhb = kvb + 2 * SUB;
#pragma unroll
        for (int kc2 = 0; kc2 < 4; kc2++) {
            uint32_t phic[4], ploc[4];
#pragma unroll
            for (int h = 0; h < 2; h++) {
                const int nt = 2 * kc2 + h;
                int col = t0 + nt * 8 + tq * 2;
                float e0 = fexp(s[nt][0]), e1 = fexp(s[nt][1]);
                float e2 = fexp(s[nt][2]), e3 = fexp(s[nt][3]);
                if (msk) {
                    if (col > rg0) e0 = 0.f;
                    if (col + 1 > rg0) e1 = 0.f;
                    if (col > rg0 + 8) e2 = 0.f;
                    if (col + 1 > rg0 + 8) e3 = 0.f;
                }
                la0 += e0 + e1;
                la1 += e2 + e3;
                __nv_bfloat16 h0, l0, h1, l1, h2, l2, h3, l3;
                splitf(e0, h0, l0); splitf(e1, h1, l1);
                splitf(e2, h2, l2); splitf(e3, h3, l3);
                phic[h * 2 + 0] = b2u(h0, h1);
                phic[h * 2 + 1] = b2u(h2, h3);
                ploc[h * 2 + 0] = b2u(l0, l1);
                ploc[h * 2 + 1] = b2u(l2, l3);
            }
#pragma unroll
            for (int ng = 0; ng < 2; ng++) {        // nh groups of 4
                uint32_t vh[4][4], vl[4][4];
#pragma unroll
                for (int j = 0; j < 4; j++) {
                    uint32_t va = vhb + voff + kc2 * (16 * STR) + (ng * 4 + j) * 32;
                    LDSM4T(vh[j], va);
                    LDSM4T(vl[j], va + SUB);
                }
#pragma unroll
                for (int j = 0; j < 4; j++) {       // pass 1: phi * vhi
                    MMA(o[2 * (ng * 4 + j)], phic, vh[j]);
                    MMA(o[2 * (ng * 4 + j) + 1], phic, vh[j] + 2);
                }
#pragma unroll
                for (int j = 0; j < 4; j++) {       // pass 2: phi * vlo
                    MMA(o[2 * (ng * 4 + j)], phic, vl[j]);
                    MMA(o[2 * (ng * 4 + j) + 1], phic, vl[j] + 2);
                }
#pragma unroll
                for (int j = 0; j < 4; j++) {       // pass 3: plo * vhi
                    MMA(o[2 * (ng * 4 + j)], ploc, vh[j]);
                    MMA(o[2 * (ng * 4 + j) + 1], ploc, vh[j] + 2);
                }
            }
        }
    }

    la0 += __shfl_xor_sync(0xffffffffu, la0, 1);
    la0 += __shfl_xor_sync(0xffffffffu, la0, 2);
    la1 += __shfl_xor_sync(0xffffffffu, la1, 1);
    la1 += __shfl_xor_sync(0xffffffffu, la1, 2);
    const float rl0 = 1.f / la0, rl1 = 1.f / la1;
    float* o0 = Out + (gq0 + w * 16 + gl) * HDIM + tq * 2;
    float* o1 = o0 + 8 * HDIM;
#pragma unroll
    for (int nt2 = 0; nt2 < 16; nt2++) {
        *(float2*)(o0 + nt2 * 8) = make_float2(o[nt2][0] * rl0, o[nt2][1] * rl0);
        *(float2*)(o1 + nt2 * 8) = make_float2(o[nt2][2] * rl1, o[nt2][3] * rl1);
    }
}

// ---------------------------------------------------------------------------
extern "C" void kernel_launch(void* const* d_in, const int* in_sizes, int n_in,
                              void* d_out, int out_size) {
    const float* x  = (const float*)d_in[0];
    const float* Wq = (const float*)d_in[1];
    const float* Wk = (const float*)d_in[2];
    const float* Wv = (const float*)d_in[3];
    float* out = (float*)d_out;
    (void)in_sizes; (void)n_in; (void)out_size;

    split_w<<<96, 512>>>(Wq, Wk, Wv);

    cudaFuncSetAttribute(proj_mma, cudaFuncAttributeMaxDynamicSharedMemorySize, PSM_TOT);
    proj_mma<<<dim3(256, 3), 256, PSM_TOT>>>(x);

    cudaFuncSetAttribute(flash_mma, cudaFuncAttributeMaxDynamicSharedMemorySize, SM_TOT);
    flash_mma<<<dim3(BSZ, 32), 256, SM_TOT>>>(out);
}